// round 1
// baseline (speedup 1.0000x reference)
#include <cuda_runtime.h>
#include <cstdint>

// Problem shape (fixed by the dataset)
#define DD 128
#define MAXN 10000
#define MAXE 80000

// ---------------- device scratch (no allocations allowed) ----------------
__device__ float g_lgX[MAXE * DD];      // line-graph node features [E,128]
__device__ float g_A[MAXN * DD];        // per-node aggregate       [N,128]
__device__ int   g_off[MAXN + 1];       // in-CSR offsets
__device__ int   g_cursor[MAXN];
__device__ int   g_cnt[MAXN];           // in-degree (== scatter_mean count)
__device__ int   g_inedges[MAXE];       // in-CSR edge ids

// ---------------- f32x2 helpers (FFMA2) ----------------
__device__ __forceinline__ unsigned long long pack2(float a) {
    unsigned long long r;
    asm("mov.b64 %0, {%1, %1};" : "=l"(r) : "f"(a));
    return r;
}
__device__ __forceinline__ void fma2(unsigned long long& d,
                                     unsigned long long a,
                                     unsigned long long b) {
    asm("fma.rn.f32x2 %0, %1, %2, %0;" : "+l"(d) : "l"(a), "l"(b));
}
__device__ __forceinline__ float2 unpack2(unsigned long long v) {
    float2 f;
    asm("mov.b64 {%0, %1}, %2;" : "=f"(f.x), "=f"(f.y) : "l"(v));
    return f;
}

// ---------------- CSR build ----------------
__global__ void zero_cnt_kernel(int n) {
    int i = blockIdx.x * blockDim.x + threadIdx.x;
    if (i < n) g_cnt[i] = 0;
}

__global__ void count_kernel(const int* __restrict__ dst, int E) {
    int i = blockIdx.x * blockDim.x + threadIdx.x;
    if (i < E) atomicAdd(&g_cnt[dst[i]], 1);
}

__global__ void scan_kernel(int n) {
    __shared__ int part[1024];
    int tid = threadIdx.x;
    int C = (n + 1023) >> 10;
    int beg = tid * C;
    int s = 0;
    for (int j = 0; j < C; j++) {
        int id = beg + j;
        if (id < n) s += g_cnt[id];
    }
    part[tid] = s;
    __syncthreads();
    for (int d = 1; d < 1024; d <<= 1) {
        int v = (tid >= d) ? part[tid - d] : 0;
        __syncthreads();
        part[tid] += v;
        __syncthreads();
    }
    int run = (tid > 0) ? part[tid - 1] : 0;
    for (int j = 0; j < C; j++) {
        int id = beg + j;
        if (id < n) {
            g_off[id] = run;
            g_cursor[id] = run;
            run += g_cnt[id];
        }
    }
    if (tid == 0) g_off[n] = part[1023];
}

__global__ void fill_kernel(const int* __restrict__ dst, int E) {
    int i = blockIdx.x * blockDim.x + threadIdx.x;
    if (i < E) {
        int v = dst[i];
        int p = atomicAdd(&g_cursor[v], 1);
        g_inedges[p] = i;
    }
}

// ---------------- init: lgX = 0.5*(x[src]+x[dst]) ----------------
__global__ void init_kernel(const float* __restrict__ x,
                            const int* __restrict__ src,
                            const int* __restrict__ dst, int E) {
    int gid = blockIdx.x * blockDim.x + threadIdx.x;
    if (gid >= E * 32) return;
    int row = gid >> 5;
    int lane = gid & 31;
    const float4* x4 = (const float4*)x;
    float4 a = x4[src[row] * 32 + lane];
    float4 b = x4[dst[row] * 32 + lane];
    float4 o;
    o.x = 0.5f * (a.x + b.x);
    o.y = 0.5f * (a.y + b.y);
    o.z = 0.5f * (a.z + b.z);
    o.w = 0.5f * (a.w + b.w);
    ((float4*)g_lgX)[gid] = o;
}

// ---------------- aggregation: A[v] = sum over in-edges relu(lgX[i]+x[v]) ----------------
__global__ void __launch_bounds__(256) agg_kernel(const float* __restrict__ x, int Nn) {
    int w = (blockIdx.x * blockDim.x + threadIdx.x) >> 5;
    int lane = threadIdx.x & 31;
    if (w >= Nn) return;
    const float4* x4 = (const float4*)x;
    float4 xv = x4[w * 32 + lane];
    float4 acc = make_float4(0.f, 0.f, 0.f, 0.f);
    int e0 = g_off[w], e1 = g_off[w + 1];
    for (int e = e0; e < e1; e++) {
        int i = g_inedges[e];
        float4 l = *(const float4*)(g_lgX + i * DD + lane * 4);
        acc.x += fmaxf(l.x + xv.x, 0.f);
        acc.y += fmaxf(l.y + xv.y, 0.f);
        acc.z += fmaxf(l.z + xv.z, 0.f);
        acc.w += fmaxf(l.w + xv.w, 0.f);
    }
    *(float4*)(g_A + w * DD + lane * 4) = acc;
}

// ---------------- fused h -> relu(h@W1+b1)@W2+b2, in-place on lgX ----------------
// tile: 64 rows x 128 cols, 256 threads, per-thread micro-tile 4x8 (f32x2 pairs)
#define HP 132
#define SMEM_FLOATS (16384 * 2 + 64 * HP)
#define SMEM_BYTES (SMEM_FLOATS * 4)

__global__ void __launch_bounds__(256, 1)
gemm_kernel(const int* __restrict__ src,
            const float* __restrict__ W1, const float* __restrict__ b1,
            const float* __restrict__ W2, const float* __restrict__ b2) {
    extern __shared__ float sm[];
    float* Ws1 = sm;                 // [128][128]
    float* Ws2 = sm + 16384;         // [128][128]
    float* Hs  = sm + 32768;         // [64][HP]

    int tid = threadIdx.x;
    int base = blockIdx.x * 64;

    // load weights (both resident)
    {
        const float4* w1v = (const float4*)W1;
        const float4* w2v = (const float4*)W2;
        float4* s1v = (float4*)Ws1;
        float4* s2v = (float4*)Ws2;
        for (int idx = tid; idx < 4096; idx += 256) {
            s1v[idx] = w1v[idx];
            s2v[idx] = w2v[idx];
        }
    }
    // load H tile: h = lgX[row] + A[src[row]]
    for (int idx = tid; idx < 64 * 128; idx += 256) {
        int r = idx >> 7, k = idx & 127;
        int row = base + r;
        Hs[r * HP + k] = g_lgX[row * DD + k] + g_A[src[row] * DD + k];
    }
    __syncthreads();

    int tx = tid & 15, ty = tid >> 4;
    int cx = tx * 8;       // 8 consecutive output cols
    int ry = ty * 4;       // 4 consecutive rows

    float bb1[8], bb2[8];
#pragma unroll
    for (int j = 0; j < 8; j++) {
        bb1[j] = b1[cx + j];
        bb2[j] = b2[cx + j];
    }

    unsigned long long acc[4][4];
#pragma unroll
    for (int r = 0; r < 4; r++)
#pragma unroll
        for (int c = 0; c < 4; c++) acc[r][c] = 0ull;

    // GEMM1: T = relu(H @ W1 + b1)
#pragma unroll 4
    for (int k = 0; k < 128; ++k) {
        const float* wr = Ws1 + k * 128 + cx;
        ulonglong2 B0 = *reinterpret_cast<const ulonglong2*>(wr);
        ulonglong2 B1 = *reinterpret_cast<const ulonglong2*>(wr + 4);
#pragma unroll
        for (int r = 0; r < 4; ++r) {
            unsigned long long av = pack2(Hs[(ry + r) * HP + k]);
            fma2(acc[r][0], av, B0.x);
            fma2(acc[r][1], av, B0.y);
            fma2(acc[r][2], av, B1.x);
            fma2(acc[r][3], av, B1.y);
        }
    }
    __syncthreads();   // all reads of Hs complete -> safe to overwrite with T

#pragma unroll
    for (int r = 0; r < 4; ++r) {
        float2 f0 = unpack2(acc[r][0]);
        float2 f1 = unpack2(acc[r][1]);
        float2 f2 = unpack2(acc[r][2]);
        float2 f3 = unpack2(acc[r][3]);
        float4 s0, s1;
        s0.x = fmaxf(f0.x + bb1[0], 0.f);
        s0.y = fmaxf(f0.y + bb1[1], 0.f);
        s0.z = fmaxf(f1.x + bb1[2], 0.f);
        s0.w = fmaxf(f1.y + bb1[3], 0.f);
        s1.x = fmaxf(f2.x + bb1[4], 0.f);
        s1.y = fmaxf(f2.y + bb1[5], 0.f);
        s1.z = fmaxf(f3.x + bb1[6], 0.f);
        s1.w = fmaxf(f3.y + bb1[7], 0.f);
        *(float4*)(Hs + (ry + r) * HP + cx) = s0;
        *(float4*)(Hs + (ry + r) * HP + cx + 4) = s1;
#pragma unroll
        for (int c = 0; c < 4; c++) acc[r][c] = 0ull;
    }
    __syncthreads();

    // GEMM2: lgX = T @ W2 + b2
#pragma unroll 4
    for (int k = 0; k < 128; ++k) {
        const float* wr = Ws2 + k * 128 + cx;
        ulonglong2 B0 = *reinterpret_cast<const ulonglong2*>(wr);
        ulonglong2 B1 = *reinterpret_cast<const ulonglong2*>(wr + 4);
#pragma unroll
        for (int r = 0; r < 4; ++r) {
            unsigned long long av = pack2(Hs[(ry + r) * HP + k]);
            fma2(acc[r][0], av, B0.x);
            fma2(acc[r][1], av, B0.y);
            fma2(acc[r][2], av, B1.x);
            fma2(acc[r][3], av, B1.y);
        }
    }

#pragma unroll
    for (int r = 0; r < 4; ++r) {
        float2 f0 = unpack2(acc[r][0]);
        float2 f1 = unpack2(acc[r][1]);
        float2 f2 = unpack2(acc[r][2]);
        float2 f3 = unpack2(acc[r][3]);
        float4 s0, s1;
        s0.x = f0.x + bb2[0];
        s0.y = f0.y + bb2[1];
        s0.z = f1.x + bb2[2];
        s0.w = f1.y + bb2[3];
        s1.x = f2.x + bb2[4];
        s1.y = f2.y + bb2[5];
        s1.z = f3.x + bb2[6];
        s1.w = f3.y + bb2[7];
        int row = base + ry + r;
        *(float4*)(g_lgX + row * DD + cx) = s0;
        *(float4*)(g_lgX + row * DD + cx + 4) = s1;
    }
}

// ---------------- output: relu(scatter_mean over dst) ----------------
__global__ void __launch_bounds__(256) out_kernel(float* __restrict__ out, int Nn) {
    int w = (blockIdx.x * blockDim.x + threadIdx.x) >> 5;
    int lane = threadIdx.x & 31;
    if (w >= Nn) return;
    float4 acc = make_float4(0.f, 0.f, 0.f, 0.f);
    int e0 = g_off[w], e1 = g_off[w + 1];
    for (int e = e0; e < e1; e++) {
        int i = g_inedges[e];
        float4 l = *(const float4*)(g_lgX + i * DD + lane * 4);
        acc.x += l.x;
        acc.y += l.y;
        acc.z += l.z;
        acc.w += l.w;
    }
    float inv = 1.0f / fmaxf((float)g_cnt[w], 1.0f);
    float4 o;
    o.x = fmaxf(acc.x * inv, 0.f);
    o.y = fmaxf(acc.y * inv, 0.f);
    o.z = fmaxf(acc.z * inv, 0.f);
    o.w = fmaxf(acc.w * inv, 0.f);
    *(float4*)(out + w * DD + lane * 4) = o;
}

// ---------------- launcher ----------------
extern "C" void kernel_launch(void* const* d_in, const int* in_sizes, int n_in,
                              void* d_out, int out_size) {
    const float* x  = (const float*)d_in[0];
    const int*   ei = (const int*)d_in[1];
    const float* W1 = (const float*)d_in[4];
    const float* b1 = (const float*)d_in[5];
    const float* W2 = (const float*)d_in[6];
    const float* b2 = (const float*)d_in[7];
    float* out = (float*)d_out;

    int E  = in_sizes[1] / 2;
    int Nn = in_sizes[0] / DD;
    const int* src = ei;
    const int* dst = ei + E;

    cudaFuncSetAttribute(gemm_kernel,
                         cudaFuncAttributeMaxDynamicSharedMemorySize, SMEM_BYTES);

    // CSR build (by dst)
    zero_cnt_kernel<<<(Nn + 255) / 256, 256>>>(Nn);
    count_kernel<<<(E + 255) / 256, 256>>>(dst, E);
    scan_kernel<<<1, 1024>>>(Nn);
    fill_kernel<<<(E + 255) / 256, 256>>>(dst, E);

    // lgX init
    init_kernel<<<(E * 32 + 255) / 256, 256>>>(x, src, dst, E);

    // 3x GINEConv
    for (int it = 0; it < 3; ++it) {
        agg_kernel<<<(Nn * 32 + 255) / 256, 256>>>(x, Nn);
        gemm_kernel<<<E / 64, 256, SMEM_BYTES>>>(src, W1, b1, W2, b2);
    }

    // output
    out_kernel<<<(Nn * 32 + 255) / 256, 256>>>(out, Nn);
}

// round 3
// speedup vs baseline: 2.7562x; 2.7562x over previous
#include <cuda_runtime.h>
#include <cuda_bf16.h>
#include <cstdint>

// Problem shape (fixed by the dataset)
#define DD 128
#define MAXN 10000
#define MAXE 80000

// ---------------- device scratch ----------------
__device__ float g_lgX[MAXE * DD];            // line-graph node features [E,128]
__device__ float g_A[MAXN * DD];              // per-node aggregate       [N,128]
__device__ int   g_off[MAXN + 1];
__device__ int   g_cursor[MAXN];
__device__ int   g_cnt[MAXN];
__device__ int   g_inedges[MAXE];
// W images: [W1hi | W1lo | W2hi | W2lo]; each 128x128 bf16 stored transposed
// (BT[n][k] = W[k][n]) in two 64-col K-chunks of 16KB, SW128-swizzled rows.
__device__ __nv_bfloat16 g_Wimg[4 * 16384];

#define SWZ(x) ((x) ^ (((x) >> 3) & 0x70))

__device__ __forceinline__ uint32_t smem_u32(const void* p) {
    uint32_t a;
    asm("{ .reg .u64 t; cvta.to.shared.u64 t, %1; cvt.u32.u64 %0, t; }" : "=r"(a) : "l"(p));
    return a;
}
__device__ __forceinline__ void ldsm4(uint32_t* r, uint32_t addr) {
    asm volatile("ldmatrix.sync.aligned.m8n8.x4.shared.b16 {%0,%1,%2,%3}, [%4];"
        : "=r"(r[0]), "=r"(r[1]), "=r"(r[2]), "=r"(r[3]) : "r"(addr));
}
__device__ __forceinline__ void mma16816(float* c, const uint32_t* a, const uint32_t* b) {
    asm volatile("mma.sync.aligned.m16n8k16.row.col.f32.bf16.bf16.f32 "
        "{%0,%1,%2,%3}, {%4,%5,%6,%7}, {%8,%9}, {%0,%1,%2,%3};"
        : "+f"(c[0]), "+f"(c[1]), "+f"(c[2]), "+f"(c[3])
        : "r"(a[0]), "r"(a[1]), "r"(a[2]), "r"(a[3]), "r"(b[0]), "r"(b[1]));
}

// ---------------- CSR build ----------------
__global__ void zero_cnt_kernel(int n) {
    int i = blockIdx.x * blockDim.x + threadIdx.x;
    if (i < n) g_cnt[i] = 0;
}
__global__ void count_kernel(const int* __restrict__ dst, int E) {
    int i = blockIdx.x * blockDim.x + threadIdx.x;
    if (i < E) atomicAdd(&g_cnt[dst[i]], 1);
}
__global__ void scan_kernel(int n) {
    __shared__ int part[1024];
    int tid = threadIdx.x;
    int C = (n + 1023) >> 10;
    int beg = tid * C;
    int s = 0;
    for (int j = 0; j < C; j++) { int id = beg + j; if (id < n) s += g_cnt[id]; }
    part[tid] = s;
    __syncthreads();
    for (int d = 1; d < 1024; d <<= 1) {
        int v = (tid >= d) ? part[tid - d] : 0;
        __syncthreads();
        part[tid] += v;
        __syncthreads();
    }
    int run = (tid > 0) ? part[tid - 1] : 0;
    for (int j = 0; j < C; j++) {
        int id = beg + j;
        if (id < n) { g_off[id] = run; g_cursor[id] = run; run += g_cnt[id]; }
    }
    if (tid == 0) g_off[n] = part[1023];
}
__global__ void fill_kernel(const int* __restrict__ dst, int E) {
    int i = blockIdx.x * blockDim.x + threadIdx.x;
    if (i < E) { int v = dst[i]; int p = atomicAdd(&g_cursor[v], 1); g_inedges[p] = i; }
}

// ---------------- W image precompute ----------------
__global__ void prep_w_kernel(const float* __restrict__ W1, const float* __restrict__ W2) {
    int idx = blockIdx.x * blockDim.x + threadIdx.x;   // 0..16383
    if (idx >= 16384) return;
    int n = idx >> 7, k = idx & 127;
    int chunk = k >> 6, kk = k & 63;
    int boff = n * 128 + kk * 2;
    int pos = chunk * 8192 + (SWZ(boff) >> 1);          // element index within tile
    float w1 = W1[k * 128 + n];
    __nv_bfloat16 h1 = __float2bfloat16(w1);
    g_Wimg[pos]             = h1;
    g_Wimg[16384 + pos]     = __float2bfloat16(w1 - __bfloat162float(h1));
    float w2 = W2[k * 128 + n];
    __nv_bfloat16 h2 = __float2bfloat16(w2);
    g_Wimg[32768 + pos]     = h2;
    g_Wimg[49152 + pos]     = __float2bfloat16(w2 - __bfloat162float(h2));
}

// ---------------- init: lgX = 0.5*(x[src]+x[dst]) ----------------
__global__ void init_kernel(const float* __restrict__ x,
                            const int* __restrict__ src,
                            const int* __restrict__ dst, int E) {
    int gid = blockIdx.x * blockDim.x + threadIdx.x;
    if (gid >= E * 32) return;
    int row = gid >> 5;
    int lane = gid & 31;
    const float4* x4 = (const float4*)x;
    float4 a = x4[src[row] * 32 + lane];
    float4 b = x4[dst[row] * 32 + lane];
    float4 o;
    o.x = 0.5f * (a.x + b.x);
    o.y = 0.5f * (a.y + b.y);
    o.z = 0.5f * (a.z + b.z);
    o.w = 0.5f * (a.w + b.w);
    ((float4*)g_lgX)[gid] = o;
}

// ---------------- aggregation ----------------
__global__ void __launch_bounds__(256) agg_kernel(const float* __restrict__ x, int Nn) {
    int w = (blockIdx.x * blockDim.x + threadIdx.x) >> 5;
    int lane = threadIdx.x & 31;
    if (w >= Nn) return;
    const float4* x4 = (const float4*)x;
    float4 xv = x4[w * 32 + lane];
    float4 acc = make_float4(0.f, 0.f, 0.f, 0.f);
    int e0 = g_off[w], e1 = g_off[w + 1];
    for (int e = e0; e < e1; e++) {
        int i = g_inedges[e];
        float4 l = *(const float4*)(g_lgX + i * DD + lane * 4);
        acc.x += fmaxf(l.x + xv.x, 0.f);
        acc.y += fmaxf(l.y + xv.y, 0.f);
        acc.z += fmaxf(l.z + xv.z, 0.f);
        acc.w += fmaxf(l.w + xv.w, 0.f);
    }
    *(float4*)(g_A + w * DD + lane * 4) = acc;
}

// ---------------- fused MLP via HMMA (mma.sync bf16, 3-term split) ----------------
// SMEM layout (bytes):
#define SM_W    0                    // W1hi 32K | W1lo 32K | W2hi 32K | W2lo 32K
#define SM_H    131072               // H hi: 2 chunks x 16KB, SW128
#define SM_HLO  163840               // H lo: 32KB
#define SM_B1   196608               // float b1[128]
#define SM_B2   197120               // float b2[128]
#define SM_TOTAL 197632

// 3-term split GEMM: acc += [Ahi|Alo] x [Bhi|Blo] (hi*hi + hi*lo + lo*hi)
__device__ __forceinline__ void gemm128(
    uint32_t aHi, uint32_t aLo, uint32_t bHi, uint32_t bLo,
    int lane, int m_warp, int n_warp, float acc[2][8][4])
{
    int sub = lane >> 3, rr = lane & 7;
    int a_row = m_warp + ((sub & 1) << 3) + rr;     // + mt*16
    int a_kof = (sub >> 1) << 3;
    int b_n   = n_warp + ((sub >> 1) << 3) + rr;    // + ntp*16
    int b_kof = (sub & 1) << 3;

#pragma unroll 1
    for (int t = 0; t < 3; ++t) {
        uint32_t A = (t == 2) ? aLo : aHi;
        uint32_t B = (t == 1) ? bLo : bHi;
#pragma unroll
        for (int ks = 0; ks < 8; ++ks) {
            int kc = ks >> 2;                        // 64-col chunk
            int ka = ks * 16 + a_kof;
            int kb = ks * 16 + b_kof;
            uint32_t aaddr = A + (kc << 14) + SWZ(a_row * 128 + (ka & 63) * 2);
            uint32_t baddr = B + (kc << 14) + SWZ(b_n * 128 + (kb & 63) * 2);
            uint32_t a0[4], a1[4];
            ldsm4(a0, aaddr);
            ldsm4(a1, aaddr + 2048);                 // +16 rows (swizzle-invariant)
            uint32_t bf[4][4];
#pragma unroll
            for (int p = 0; p < 4; ++p) ldsm4(bf[p], baddr + p * 2048);
#pragma unroll
            for (int p = 0; p < 4; ++p) {
#pragma unroll
                for (int h = 0; h < 2; ++h) {
                    int nt = p * 2 + h;
                    mma16816(acc[0][nt], a0, &bf[p][h * 2]);
                    mma16816(acc[1][nt], a1, &bf[p][h * 2]);
                }
            }
        }
    }
}

__global__ void __launch_bounds__(256, 1)
mlp_kernel(const int* __restrict__ src,
           const float* __restrict__ b1, const float* __restrict__ b2) {
    extern __shared__ char smem[];
    uint32_t smem_base = smem_u32(smem);
    int tid = threadIdx.x;
    int wid = tid >> 5;
    int lane = tid & 31;
    int base = blockIdx.x * 128;

    float* b1s = (float*)(smem + SM_B1);
    float* b2s = (float*)(smem + SM_B2);
    if (tid < 128) { b1s[tid] = b1[tid]; b2s[tid] = b2[tid]; }

    // copy weight images (131072 bytes)
    {
        const float4* ws = (const float4*)g_Wimg;
        float4* wd = (float4*)(smem + SM_W);
        for (int i = tid; i < 8192; i += 256) wd[i] = ws[i];
    }

    // build H tile (hi/lo bf16, SW128-swizzled, 2 K-chunks)
#pragma unroll 1
    for (int j = 0; j < 8; ++j) {
        int g = j * 256 + tid;           // 0..2047 groups of 8 cols
        int m = g >> 4;
        int k0 = (g & 15) * 8;
        int row = base + m;
        int s = __ldg(&src[row]);
        const float4* l4 = (const float4*)(g_lgX + (size_t)row * DD + k0);
        const float4* a4 = (const float4*)(g_A + (size_t)s * DD + k0);
        float4 p = l4[0], q = l4[1], pa = a4[0], qa = a4[1];
        float v[8] = {p.x + pa.x, p.y + pa.y, p.z + pa.z, p.w + pa.w,
                      q.x + qa.x, q.y + qa.y, q.z + qa.z, q.w + qa.w};
        uint32_t hw[4], lw[4];
#pragma unroll
        for (int t = 0; t < 4; ++t) {
            __nv_bfloat162 h2 = __float22bfloat162_rn(make_float2(v[2 * t], v[2 * t + 1]));
            float rx = v[2 * t]     - __bfloat162float(h2.x);
            float ry = v[2 * t + 1] - __bfloat162float(h2.y);
            __nv_bfloat162 l2 = __float22bfloat162_rn(make_float2(rx, ry));
            hw[t] = *reinterpret_cast<uint32_t*>(&h2);
            lw[t] = *reinterpret_cast<uint32_t*>(&l2);
        }
        int ch = k0 >> 6;
        int boff = m * 128 + (k0 & 63) * 2;
        int sw = SWZ(boff);
        *(uint4*)(smem + SM_H + ch * 16384 + sw)   = make_uint4(hw[0], hw[1], hw[2], hw[3]);
        *(uint4*)(smem + SM_HLO + ch * 16384 + sw) = make_uint4(lw[0], lw[1], lw[2], lw[3]);
    }
    __syncthreads();

    int m_warp = (wid >> 1) * 32;
    int n_warp = (wid & 1) * 64;
    int ql = lane & 3, qr = lane >> 2;

    float acc[2][8][4];
#pragma unroll
    for (int mt = 0; mt < 2; ++mt)
#pragma unroll
        for (int nt = 0; nt < 8; ++nt)
#pragma unroll
            for (int c = 0; c < 4; ++c) acc[mt][nt][c] = 0.f;

    // GEMM1: T = H @ W1
    gemm128(smem_base + SM_H, smem_base + SM_HLO,
            smem_base + SM_W, smem_base + SM_W + 32768,
            lane, m_warp, n_warp, acc);
    __syncthreads();   // all ldmatrix reads of H done before overwrite

    // epilogue 1: T = relu(acc + b1) -> bf16 hi/lo back into H images
#pragma unroll
    for (int mt = 0; mt < 2; ++mt) {
#pragma unroll
        for (int nt = 0; nt < 8; ++nt) {
            int col = n_warp + nt * 8 + ql * 2;
            float2 bb = *(const float2*)(b1s + col);
            int ch = col >> 6;
            int cbyte = (col & 63) * 2;
#pragma unroll
            for (int h = 0; h < 2; ++h) {
                int row = m_warp + mt * 16 + qr + h * 8;
                float vx = fmaxf(acc[mt][nt][h * 2]     + bb.x, 0.f);
                float vy = fmaxf(acc[mt][nt][h * 2 + 1] + bb.y, 0.f);
                __nv_bfloat162 h2 = __float22bfloat162_rn(make_float2(vx, vy));
                float rx = vx - __bfloat162float(h2.x);
                float ry = vy - __bfloat162float(h2.y);
                __nv_bfloat162 l2 = __float22bfloat162_rn(make_float2(rx, ry));
                int sw = SWZ(row * 128 + cbyte);
                *(uint32_t*)(smem + SM_H + ch * 16384 + sw)   = *reinterpret_cast<uint32_t*>(&h2);
                *(uint32_t*)(smem + SM_HLO + ch * 16384 + sw) = *reinterpret_cast<uint32_t*>(&l2);
                acc[mt][nt][h * 2] = 0.f;
                acc[mt][nt][h * 2 + 1] = 0.f;
            }
        }
    }
    __syncthreads();

    // GEMM2: out = T @ W2
    gemm128(smem_base + SM_H, smem_base + SM_HLO,
            smem_base + SM_W + 65536, smem_base + SM_W + 98304,
            lane, m_warp, n_warp, acc);

    // epilogue 2: lgX = acc + b2 (direct global store, float2 per lane)
#pragma unroll
    for (int mt = 0; mt < 2; ++mt) {
#pragma unroll
        for (int nt = 0; nt < 8; ++nt) {
            int col = n_warp + nt * 8 + ql * 2;
            float2 bb = *(const float2*)(b2s + col);
#pragma unroll
            for (int h = 0; h < 2; ++h) {
                int row = base + m_warp + mt * 16 + qr + h * 8;
                float2 o;
                o.x = acc[mt][nt][h * 2]     + bb.x;
                o.y = acc[mt][nt][h * 2 + 1] + bb.y;
                *(float2*)(g_lgX + (size_t)row * DD + col) = o;
            }
        }
    }
}

// ---------------- output: relu(scatter_mean over dst) ----------------
__global__ void __launch_bounds__(256) out_kernel(float* __restrict__ out, int Nn) {
    int w = (blockIdx.x * blockDim.x + threadIdx.x) >> 5;
    int lane = threadIdx.x & 31;
    if (w >= Nn) return;
    float4 acc = make_float4(0.f, 0.f, 0.f, 0.f);
    int e0 = g_off[w], e1 = g_off[w + 1];
    for (int e = e0; e < e1; e++) {
        int i = g_inedges[e];
        float4 l = *(const float4*)(g_lgX + i * DD + lane * 4);
        acc.x += l.x; acc.y += l.y; acc.z += l.z; acc.w += l.w;
    }
    float inv = 1.0f / fmaxf((float)g_cnt[w], 1.0f);
    float4 o;
    o.x = fmaxf(acc.x * inv, 0.f);
    o.y = fmaxf(acc.y * inv, 0.f);
    o.z = fmaxf(acc.z * inv, 0.f);
    o.w = fmaxf(acc.w * inv, 0.f);
    *(float4*)(out + w * DD + lane * 4) = o;
}

// ---------------- launcher ----------------
extern "C" void kernel_launch(void* const* d_in, const int* in_sizes, int n_in,
                              void* d_out, int out_size) {
    const float* x  = (const float*)d_in[0];
    const int*   ei = (const int*)d_in[1];
    const float* W1 = (const float*)d_in[4];
    const float* b1 = (const float*)d_in[5];
    const float* W2 = (const float*)d_in[6];
    const float* b2 = (const float*)d_in[7];
    float* out = (float*)d_out;

    int E  = in_sizes[1] / 2;
    int Nn = in_sizes[0] / DD;
    const int* src = ei;
    const int* dst = ei + E;

    cudaFuncSetAttribute(mlp_kernel,
                         cudaFuncAttributeMaxDynamicSharedMemorySize, SM_TOTAL);

    prep_w_kernel<<<64, 256>>>(W1, W2);

    zero_cnt_kernel<<<(Nn + 255) / 256, 256>>>(Nn);
    count_kernel<<<(E + 255) / 256, 256>>>(dst, E);
    scan_kernel<<<1, 1024>>>(Nn);
    fill_kernel<<<(E + 255) / 256, 256>>>(dst, E);

    init_kernel<<<(E * 32 + 255) / 256, 256>>>(x, src, dst, E);

    for (int it = 0; it < 3; ++it) {
        agg_kernel<<<(Nn * 32 + 255) / 256, 256>>>(x, Nn);
        mlp_kernel<<<E / 128, 256, SM_TOTAL>>>(src, b1, b2);
    }

    out_kernel<<<(Nn * 32 + 255) / 256, 256>>>(out, Nn);
}

// round 4
// speedup vs baseline: 3.1829x; 1.1548x over previous
#include <cuda_runtime.h>
#include <cuda_bf16.h>
#include <cstdint>

// Problem shape (fixed by the dataset)
#define DD 128
#define MAXN 10000
#define MAXE 80000
#define CAP 128           // in-degree bucket capacity (indeg ~ Poisson(8))

// ---------------- device scratch ----------------
__device__ float g_lgX[MAXE * DD];            // line-graph node features [E,128]
__device__ float g_A[MAXN * DD];              // per-node aggregate       [N,128]
__device__ int   g_cnt[MAXN];                 // in-degree
__device__ int   g_buckets[MAXN * CAP];       // in-edge ids per node
// W images: [W1hi | W1lo | W2hi | W2lo]; each 128x128 bf16 stored transposed
// (BT[n][k] = W[k][n]) in two 64-col K-chunks of 16KB, SW128-swizzled rows.
__device__ __nv_bfloat16 g_Wimg[4 * 16384];

#define SWZ(x) ((x) ^ (((x) >> 3) & 0x70))

__device__ __forceinline__ uint32_t smem_u32(const void* p) {
    uint32_t a;
    asm("{ .reg .u64 t; cvta.to.shared.u64 t, %1; cvt.u32.u64 %0, t; }" : "=r"(a) : "l"(p));
    return a;
}
__device__ __forceinline__ void ldsm4(uint32_t* r, uint32_t addr) {
    asm volatile("ldmatrix.sync.aligned.m8n8.x4.shared.b16 {%0,%1,%2,%3}, [%4];"
        : "=r"(r[0]), "=r"(r[1]), "=r"(r[2]), "=r"(r[3]) : "r"(addr));
}
__device__ __forceinline__ void mma16816(float* c, const uint32_t* a, const uint32_t* b) {
    asm volatile("mma.sync.aligned.m16n8k16.row.col.f32.bf16.bf16.f32 "
        "{%0,%1,%2,%3}, {%4,%5,%6,%7}, {%8,%9}, {%0,%1,%2,%3};"
        : "+f"(c[0]), "+f"(c[1]), "+f"(c[2]), "+f"(c[3])
        : "r"(a[0]), "r"(a[1]), "r"(a[2]), "r"(a[3]), "r"(b[0]), "r"(b[1]));
}

// ---------------- bucket CSR build ----------------
__global__ void zero_cnt_kernel(int n) {
    int i = blockIdx.x * blockDim.x + threadIdx.x;
    if (i < n) g_cnt[i] = 0;
}
__global__ void fill_kernel(const int* __restrict__ dst, int E) {
    int i = blockIdx.x * blockDim.x + threadIdx.x;
    if (i < E) {
        int v = dst[i];
        int p = atomicAdd(&g_cnt[v], 1);
        if (p < CAP) g_buckets[v * CAP + p] = i;
    }
}

// ---------------- W image precompute ----------------
__global__ void prep_w_kernel(const float* __restrict__ W1, const float* __restrict__ W2) {
    int idx = blockIdx.x * blockDim.x + threadIdx.x;   // 0..16383
    if (idx >= 16384) return;
    int n = idx >> 7, k = idx & 127;
    int chunk = k >> 6, kk = k & 63;
    int boff = n * 128 + kk * 2;
    int pos = chunk * 8192 + (SWZ(boff) >> 1);
    float w1 = W1[k * 128 + n];
    __nv_bfloat16 h1 = __float2bfloat16(w1);
    g_Wimg[pos]             = h1;
    g_Wimg[16384 + pos]     = __float2bfloat16(w1 - __bfloat162float(h1));
    float w2 = W2[k * 128 + n];
    __nv_bfloat16 h2 = __float2bfloat16(w2);
    g_Wimg[32768 + pos]     = h2;
    g_Wimg[49152 + pos]     = __float2bfloat16(w2 - __bfloat162float(h2));
}

// ---------------- fused init + aggregation (iteration 0) ----------------
// lgX[i] = 0.5*(x[src[i]]+x[v]);  A[v] = sum relu(lgX[i]+x[v])
__global__ void __launch_bounds__(256) agg0_kernel(const float* __restrict__ x,
                                                   const int* __restrict__ src, int Nn) {
    int w = (blockIdx.x * blockDim.x + threadIdx.x) >> 5;
    int lane = threadIdx.x & 31;
    if (w >= Nn) return;
    const float4* x4 = (const float4*)x;
    float4 xv = x4[w * 32 + lane];
    float4 acc = make_float4(0.f, 0.f, 0.f, 0.f);
    int n = min(g_cnt[w], CAP);
    for (int e = 0; e < n; e++) {
        int i = g_buckets[w * CAP + e];
        int s = __ldg(&src[i]);
        float4 xs = x4[s * 32 + lane];
        float4 l;
        l.x = 0.5f * (xs.x + xv.x);
        l.y = 0.5f * (xs.y + xv.y);
        l.z = 0.5f * (xs.z + xv.z);
        l.w = 0.5f * (xs.w + xv.w);
        *(float4*)(g_lgX + (size_t)i * DD + lane * 4) = l;
        acc.x += fmaxf(l.x + xv.x, 0.f);
        acc.y += fmaxf(l.y + xv.y, 0.f);
        acc.z += fmaxf(l.z + xv.z, 0.f);
        acc.w += fmaxf(l.w + xv.w, 0.f);
    }
    *(float4*)(g_A + w * DD + lane * 4) = acc;
}

// ---------------- aggregation (iterations 1,2) ----------------
__global__ void __launch_bounds__(256) agg_kernel(const float* __restrict__ x, int Nn) {
    int w = (blockIdx.x * blockDim.x + threadIdx.x) >> 5;
    int lane = threadIdx.x & 31;
    if (w >= Nn) return;
    const float4* x4 = (const float4*)x;
    float4 xv = x4[w * 32 + lane];
    float4 acc = make_float4(0.f, 0.f, 0.f, 0.f);
    int n = min(g_cnt[w], CAP);
    for (int e = 0; e < n; e++) {
        int i = g_buckets[w * CAP + e];
        float4 l = *(const float4*)(g_lgX + (size_t)i * DD + lane * 4);
        acc.x += fmaxf(l.x + xv.x, 0.f);
        acc.y += fmaxf(l.y + xv.y, 0.f);
        acc.z += fmaxf(l.z + xv.z, 0.f);
        acc.w += fmaxf(l.w + xv.w, 0.f);
    }
    *(float4*)(g_A + w * DD + lane * 4) = acc;
}

// ---------------- fused MLP via HMMA (persistent, 3-term bf16 split) ----------------
#define SM_W    0                    // W1hi 32K | W1lo 32K | W2hi 32K | W2lo 32K
#define SM_H    131072               // H hi: 2 chunks x 16KB, SW128
#define SM_HLO  163840               // H lo: 32KB
#define SM_B1   196608               // float b1[128]
#define SM_B2   197120               // float b2[128]
#define SM_TOTAL 197632

__device__ __forceinline__ void gemm128(
    uint32_t aHi, uint32_t aLo, uint32_t bHi, uint32_t bLo,
    int lane, int m_warp, int n_warp, float acc[2][8][4])
{
    int sub = lane >> 3, rr = lane & 7;
    int a_row = m_warp + ((sub & 1) << 3) + rr;
    int a_kof = (sub >> 1) << 3;
    int b_n   = n_warp + ((sub >> 1) << 3) + rr;
    int b_kof = (sub & 1) << 3;

#pragma unroll 1
    for (int t = 0; t < 3; ++t) {
        uint32_t A = (t == 2) ? aLo : aHi;
        uint32_t B = (t == 1) ? bLo : bHi;
#pragma unroll
        for (int ks = 0; ks < 8; ++ks) {
            int kc = ks >> 2;
            int ka = ks * 16 + a_kof;
            int kb = ks * 16 + b_kof;
            uint32_t aaddr = A + (kc << 14) + SWZ(a_row * 128 + (ka & 63) * 2);
            uint32_t baddr = B + (kc << 14) + SWZ(b_n * 128 + (kb & 63) * 2);
            uint32_t a0[4], a1[4];
            ldsm4(a0, aaddr);
            ldsm4(a1, aaddr + 2048);
            uint32_t bf[4][4];
#pragma unroll
            for (int p = 0; p < 4; ++p) ldsm4(bf[p], baddr + p * 2048);
#pragma unroll
            for (int p = 0; p < 4; ++p) {
#pragma unroll
                for (int h = 0; h < 2; ++h) {
                    int nt = p * 2 + h;
                    mma16816(acc[0][nt], a0, &bf[p][h * 2]);
                    mma16816(acc[1][nt], a1, &bf[p][h * 2]);
                }
            }
        }
    }
}

__global__ void __launch_bounds__(256, 1)
mlp_kernel(const int* __restrict__ src,
           const float* __restrict__ b1, const float* __restrict__ b2, int ntiles) {
    extern __shared__ char smem[];
    uint32_t smem_base = smem_u32(smem);
    int tid = threadIdx.x;
    int wid = tid >> 5;
    int lane = tid & 31;

    float* b1s = (float*)(smem + SM_B1);
    float* b2s = (float*)(smem + SM_B2);
    if (tid < 128) { b1s[tid] = b1[tid]; b2s[tid] = b2[tid]; }

    // async copy of weight images (131072 bytes), overlapped with first H build
    {
        const char* ws = (const char*)g_Wimg;
        for (int i = tid; i < 8192; i += 256) {
            uint32_t d = smem_base + SM_W + i * 16;
            asm volatile("cp.async.cg.shared.global [%0], [%1], 16;"
                         :: "r"(d), "l"(ws + (size_t)i * 16) : "memory");
        }
        asm volatile("cp.async.commit_group;" ::: "memory");
    }

    int m_warp = (wid >> 1) * 32;
    int n_warp = (wid & 1) * 64;
    int ql = lane & 3, qr = lane >> 2;

    for (int tile = blockIdx.x; tile < ntiles; tile += gridDim.x) {
        int base = tile * 128;

        // build H tile (hi/lo bf16, SW128-swizzled, 2 K-chunks)
#pragma unroll 1
        for (int j = 0; j < 8; ++j) {
            int g = j * 256 + tid;           // 0..2047 groups of 8 cols
            int m = g >> 4;
            int k0 = (g & 15) * 8;
            int row = base + m;
            int s = __ldg(&src[row]);
            const float4* l4 = (const float4*)(g_lgX + (size_t)row * DD + k0);
            const float4* a4 = (const float4*)(g_A + (size_t)s * DD + k0);
            float4 p = l4[0], q = l4[1], pa = a4[0], qa = a4[1];
            float v[8] = {p.x + pa.x, p.y + pa.y, p.z + pa.z, p.w + pa.w,
                          q.x + qa.x, q.y + qa.y, q.z + qa.z, q.w + qa.w};
            uint32_t hw[4], lw[4];
#pragma unroll
            for (int t = 0; t < 4; ++t) {
                __nv_bfloat162 h2 = __float22bfloat162_rn(make_float2(v[2 * t], v[2 * t + 1]));
                float rx = v[2 * t]     - __bfloat162float(h2.x);
                float ry = v[2 * t + 1] - __bfloat162float(h2.y);
                __nv_bfloat162 l2 = __float22bfloat162_rn(make_float2(rx, ry));
                hw[t] = *reinterpret_cast<uint32_t*>(&h2);
                lw[t] = *reinterpret_cast<uint32_t*>(&l2);
            }
            int ch = k0 >> 6;
            int boff = m * 128 + (k0 & 63) * 2;
            int sw = SWZ(boff);
            *(uint4*)(smem + SM_H + ch * 16384 + sw)   = make_uint4(hw[0], hw[1], hw[2], hw[3]);
            *(uint4*)(smem + SM_HLO + ch * 16384 + sw) = make_uint4(lw[0], lw[1], lw[2], lw[3]);
        }
        asm volatile("cp.async.wait_group 0;" ::: "memory");
        __syncthreads();

        float acc[2][8][4];
#pragma unroll
        for (int mt = 0; mt < 2; ++mt)
#pragma unroll
            for (int nt = 0; nt < 8; ++nt)
#pragma unroll
                for (int c = 0; c < 4; ++c) acc[mt][nt][c] = 0.f;

        // GEMM1: T = H @ W1
        gemm128(smem_base + SM_H, smem_base + SM_HLO,
                smem_base + SM_W, smem_base + SM_W + 32768,
                lane, m_warp, n_warp, acc);
        __syncthreads();

        // epilogue 1: T = relu(acc + b1) -> bf16 hi/lo back into H images
#pragma unroll
        for (int mt = 0; mt < 2; ++mt) {
#pragma unroll
            for (int nt = 0; nt < 8; ++nt) {
                int col = n_warp + nt * 8 + ql * 2;
                float2 bb = *(const float2*)(b1s + col);
                int ch = col >> 6;
                int cbyte = (col & 63) * 2;
#pragma unroll
                for (int h = 0; h < 2; ++h) {
                    int row = m_warp + mt * 16 + qr + h * 8;
                    float vx = fmaxf(acc[mt][nt][h * 2]     + bb.x, 0.f);
                    float vy = fmaxf(acc[mt][nt][h * 2 + 1] + bb.y, 0.f);
                    __nv_bfloat162 h2 = __float22bfloat162_rn(make_float2(vx, vy));
                    float rx = vx - __bfloat162float(h2.x);
                    float ry = vy - __bfloat162float(h2.y);
                    __nv_bfloat162 l2 = __float22bfloat162_rn(make_float2(rx, ry));
                    int sw = SWZ(row * 128 + cbyte);
                    *(uint32_t*)(smem + SM_H + ch * 16384 + sw)   = *reinterpret_cast<uint32_t*>(&h2);
                    *(uint32_t*)(smem + SM_HLO + ch * 16384 + sw) = *reinterpret_cast<uint32_t*>(&l2);
                    acc[mt][nt][h * 2] = 0.f;
                    acc[mt][nt][h * 2 + 1] = 0.f;
                }
            }
        }
        __syncthreads();

        // GEMM2: out = T @ W2
        gemm128(smem_base + SM_H, smem_base + SM_HLO,
                smem_base + SM_W + 65536, smem_base + SM_W + 98304,
                lane, m_warp, n_warp, acc);

        // epilogue 2: lgX = acc + b2 (direct global store)
#pragma unroll
        for (int mt = 0; mt < 2; ++mt) {
#pragma unroll
            for (int nt = 0; nt < 8; ++nt) {
                int col = n_warp + nt * 8 + ql * 2;
                float2 bb = *(const float2*)(b2s + col);
#pragma unroll
                for (int h = 0; h < 2; ++h) {
                    int row = base + m_warp + mt * 16 + qr + h * 8;
                    float2 o;
                    o.x = acc[mt][nt][h * 2]     + bb.x;
                    o.y = acc[mt][nt][h * 2 + 1] + bb.y;
                    *(float2*)(g_lgX + (size_t)row * DD + col) = o;
                }
            }
        }
        __syncthreads();   // GEMM2 smem reads done before next tile's H build
    }
}

// ---------------- output: relu(scatter_mean over dst) ----------------
__global__ void __launch_bounds__(256) out_kernel(float* __restrict__ out, int Nn) {
    int w = (blockIdx.x * blockDim.x + threadIdx.x) >> 5;
    int lane = threadIdx.x & 31;
    if (w >= Nn) return;
    float4 acc = make_float4(0.f, 0.f, 0.f, 0.f);
    int n = min(g_cnt[w], CAP);
    for (int e = 0; e < n; e++) {
        int i = g_buckets[w * CAP + e];
        float4 l = *(const float4*)(g_lgX + (size_t)i * DD + lane * 4);
        acc.x += l.x; acc.y += l.y; acc.z += l.z; acc.w += l.w;
    }
    float inv = 1.0f / fmaxf((float)g_cnt[w], 1.0f);
    float4 o;
    o.x = fmaxf(acc.x * inv, 0.f);
    o.y = fmaxf(acc.y * inv, 0.f);
    o.z = fmaxf(acc.z * inv, 0.f);
    o.w = fmaxf(acc.w * inv, 0.f);
    *(float4*)(out + w * DD + lane * 4) = o;
}

// ---------------- launcher ----------------
extern "C" void kernel_launch(void* const* d_in, const int* in_sizes, int n_in,
                              void* d_out, int out_size) {
    const float* x  = (const float*)d_in[0];
    const int*   ei = (const int*)d_in[1];
    const float* W1 = (const float*)d_in[4];
    const float* b1 = (const float*)d_in[5];
    const float* W2 = (const float*)d_in[6];
    const float* b2 = (const float*)d_in[7];
    float* out = (float*)d_out;

    int E  = in_sizes[1] / 2;
    int Nn = in_sizes[0] / DD;
    const int* src = ei;
    const int* dst = ei + E;
    int ntiles = E / 128;

    cudaFuncSetAttribute(mlp_kernel,
                         cudaFuncAttributeMaxDynamicSharedMemorySize, SM_TOTAL);

    prep_w_kernel<<<64, 256>>>(W1, W2);
    zero_cnt_kernel<<<(Nn + 255) / 256, 256>>>(Nn);
    fill_kernel<<<(E + 255) / 256, 256>>>(dst, E);

    // iteration 0: fused init + aggregation
    agg0_kernel<<<(Nn * 32 + 255) / 256, 256>>>(x, src, Nn);
    mlp_kernel<<<152, 256, SM_TOTAL>>>(src, b1, b2, ntiles);

    for (int it = 1; it < 3; ++it) {
        agg_kernel<<<(Nn * 32 + 255) / 256, 256>>>(x, Nn);
        mlp_kernel<<<152, 256, SM_TOTAL>>>(src, b1, b2, ntiles);
    }

    out_kernel<<<(Nn * 32 + 255) / 256, 256>>>(out, Nn);
}

// round 5
// speedup vs baseline: 3.9387x; 1.2375x over previous
#include <cuda_runtime.h>
#include <cuda_fp16.h>
#include <cstdint>

// Problem shape (fixed by the dataset)
#define DD 128
#define MAXN 10000
#define MAXE 80000
#define CAP 128           // in-degree bucket capacity (indeg ~ Poisson(8))

// ---------------- device scratch ----------------
__device__ float g_lgX[MAXE * DD];            // line-graph node features [E,128]
__device__ float g_A[MAXN * DD];              // per-node aggregate       [N,128]
__device__ int   g_cnt[MAXN];                 // in-degree
__device__ int   g_buckets[MAXN * CAP];       // in-edge ids per node
// W images: [W1 | W2]; each 128x128 fp16 stored transposed (BT[n][k] = W[k][n])
// in two 64-col K-chunks of 16KB, SW128-swizzled rows.
__device__ __half g_Wimg[2 * 16384];

#define SWZ(x) ((x) ^ (((x) >> 3) & 0x70))

__device__ __forceinline__ uint32_t smem_u32(const void* p) {
    uint32_t a;
    asm("{ .reg .u64 t; cvta.to.shared.u64 t, %1; cvt.u32.u64 %0, t; }" : "=r"(a) : "l"(p));
    return a;
}
__device__ __forceinline__ void ldsm4(uint32_t* r, uint32_t addr) {
    asm volatile("ldmatrix.sync.aligned.m8n8.x4.shared.b16 {%0,%1,%2,%3}, [%4];"
        : "=r"(r[0]), "=r"(r[1]), "=r"(r[2]), "=r"(r[3]) : "r"(addr));
}
__device__ __forceinline__ void mma16816(float* c, const uint32_t* a, const uint32_t* b) {
    asm volatile("mma.sync.aligned.m16n8k16.row.col.f32.f16.f16.f32 "
        "{%0,%1,%2,%3}, {%4,%5,%6,%7}, {%8,%9}, {%0,%1,%2,%3};"
        : "+f"(c[0]), "+f"(c[1]), "+f"(c[2]), "+f"(c[3])
        : "r"(a[0]), "r"(a[1]), "r"(a[2]), "r"(a[3]), "r"(b[0]), "r"(b[1]));
}

// ---------------- bucket CSR build ----------------
__global__ void zero_cnt_kernel(int n) {
    int i = blockIdx.x * blockDim.x + threadIdx.x;
    if (i < n) g_cnt[i] = 0;
}
__global__ void fill_kernel(const int* __restrict__ dst, int E) {
    int i = blockIdx.x * blockDim.x + threadIdx.x;
    if (i < E) {
        int v = dst[i];
        int p = atomicAdd(&g_cnt[v], 1);
        if (p < CAP) g_buckets[v * CAP + p] = i;
    }
}

// ---------------- W image precompute (fp16, transposed, swizzled) ----------------
__global__ void prep_w_kernel(const float* __restrict__ W1, const float* __restrict__ W2) {
    int idx = blockIdx.x * blockDim.x + threadIdx.x;   // 0..16383
    if (idx >= 16384) return;
    int n = idx >> 7, k = idx & 127;
    int chunk = k >> 6, kk = k & 63;
    int boff = n * 128 + kk * 2;
    int pos = chunk * 8192 + (SWZ(boff) >> 1);
    g_Wimg[pos]         = __float2half(W1[k * 128 + n]);
    g_Wimg[16384 + pos] = __float2half(W2[k * 128 + n]);
}

// ---------------- fused init + aggregation (iteration 0) ----------------
__global__ void __launch_bounds__(256) agg0_kernel(const float* __restrict__ x,
                                                   const int* __restrict__ src, int Nn) {
    int w = (blockIdx.x * blockDim.x + threadIdx.x) >> 5;
    int lane = threadIdx.x & 31;
    if (w >= Nn) return;
    const float4* x4 = (const float4*)x;
    float4 xv = x4[w * 32 + lane];
    float4 acc = make_float4(0.f, 0.f, 0.f, 0.f);
    int n = min(g_cnt[w], CAP);
    int nb = min(n, 32);
    int myid = (lane < nb) ? g_buckets[w * CAP + lane] : 0;
    int mysrc = (lane < nb) ? __ldg(&src[myid]) : 0;
    int e = 0;
    for (; e + 2 <= nb; e += 2) {
        int i0 = __shfl_sync(0xffffffffu, myid, e);
        int i1 = __shfl_sync(0xffffffffu, myid, e + 1);
        int s0 = __shfl_sync(0xffffffffu, mysrc, e);
        int s1 = __shfl_sync(0xffffffffu, mysrc, e + 1);
        float4 a0 = x4[s0 * 32 + lane];
        float4 a1 = x4[s1 * 32 + lane];
        float4 l0, l1;
        l0.x = 0.5f * (a0.x + xv.x); l0.y = 0.5f * (a0.y + xv.y);
        l0.z = 0.5f * (a0.z + xv.z); l0.w = 0.5f * (a0.w + xv.w);
        l1.x = 0.5f * (a1.x + xv.x); l1.y = 0.5f * (a1.y + xv.y);
        l1.z = 0.5f * (a1.z + xv.z); l1.w = 0.5f * (a1.w + xv.w);
        *(float4*)(g_lgX + (size_t)i0 * DD + lane * 4) = l0;
        *(float4*)(g_lgX + (size_t)i1 * DD + lane * 4) = l1;
        acc.x += fmaxf(l0.x + xv.x, 0.f) + fmaxf(l1.x + xv.x, 0.f);
        acc.y += fmaxf(l0.y + xv.y, 0.f) + fmaxf(l1.y + xv.y, 0.f);
        acc.z += fmaxf(l0.z + xv.z, 0.f) + fmaxf(l1.z + xv.z, 0.f);
        acc.w += fmaxf(l0.w + xv.w, 0.f) + fmaxf(l1.w + xv.w, 0.f);
    }
    for (; e < n; e++) {
        int i0 = (e < 32) ? __shfl_sync(0xffffffffu, myid, e) : g_buckets[w * CAP + e];
        int s0 = __ldg(&src[i0]);
        float4 a0 = x4[s0 * 32 + lane];
        float4 l0;
        l0.x = 0.5f * (a0.x + xv.x); l0.y = 0.5f * (a0.y + xv.y);
        l0.z = 0.5f * (a0.z + xv.z); l0.w = 0.5f * (a0.w + xv.w);
        *(float4*)(g_lgX + (size_t)i0 * DD + lane * 4) = l0;
        acc.x += fmaxf(l0.x + xv.x, 0.f);
        acc.y += fmaxf(l0.y + xv.y, 0.f);
        acc.z += fmaxf(l0.z + xv.z, 0.f);
        acc.w += fmaxf(l0.w + xv.w, 0.f);
    }
    *(float4*)(g_A + w * DD + lane * 4) = acc;
}

// ---------------- aggregation (iterations 1,2) ----------------
__global__ void __launch_bounds__(256) agg_kernel(const float* __restrict__ x, int Nn) {
    int w = (blockIdx.x * blockDim.x + threadIdx.x) >> 5;
    int lane = threadIdx.x & 31;
    if (w >= Nn) return;
    const float4* x4 = (const float4*)x;
    float4 xv = x4[w * 32 + lane];
    float4 acc = make_float4(0.f, 0.f, 0.f, 0.f);
    int n = min(g_cnt[w], CAP);
    int nb = min(n, 32);
    int myid = (lane < nb) ? g_buckets[w * CAP + lane] : 0;
    int e = 0;
    for (; e + 2 <= nb; e += 2) {
        int i0 = __shfl_sync(0xffffffffu, myid, e);
        int i1 = __shfl_sync(0xffffffffu, myid, e + 1);
        float4 l0 = *(const float4*)(g_lgX + (size_t)i0 * DD + lane * 4);
        float4 l1 = *(const float4*)(g_lgX + (size_t)i1 * DD + lane * 4);
        acc.x += fmaxf(l0.x + xv.x, 0.f) + fmaxf(l1.x + xv.x, 0.f);
        acc.y += fmaxf(l0.y + xv.y, 0.f) + fmaxf(l1.y + xv.y, 0.f);
        acc.z += fmaxf(l0.z + xv.z, 0.f) + fmaxf(l1.z + xv.z, 0.f);
        acc.w += fmaxf(l0.w + xv.w, 0.f) + fmaxf(l1.w + xv.w, 0.f);
    }
    for (; e < n; e++) {
        int i0 = (e < 32) ? __shfl_sync(0xffffffffu, myid, e) : g_buckets[w * CAP + e];
        float4 l0 = *(const float4*)(g_lgX + (size_t)i0 * DD + lane * 4);
        acc.x += fmaxf(l0.x + xv.x, 0.f);
        acc.y += fmaxf(l0.y + xv.y, 0.f);
        acc.z += fmaxf(l0.z + xv.z, 0.f);
        acc.w += fmaxf(l0.w + xv.w, 0.f);
    }
    *(float4*)(g_A + w * DD + lane * 4) = acc;
}

// ---------------- fused MLP via fp16 HMMA (persistent, 2-term split-A) ----------------
#define SM_W    0                    // W1 32K | W2 32K (fp16)
#define SM_H    65536                // H hi: 2 chunks x 16KB, SW128
#define SM_HLO  98304                // H lo: 32KB
#define SM_B1   131072               // float b1[128]
#define SM_B2   131584               // float b2[128]
#define SM_TOTAL 132096

// D = (Ahi + Alo) @ B,  B single fp16 image
__device__ __forceinline__ void gemm128(
    uint32_t aHi, uint32_t aLo, uint32_t bB,
    int lane, int m_warp, int n_warp, float acc[2][8][4])
{
    int sub = lane >> 3, rr = lane & 7;
    int a_row = m_warp + ((sub & 1) << 3) + rr;
    int a_kof = (sub >> 1) << 3;
    int b_n   = n_warp + ((sub >> 1) << 3) + rr;
    int b_kof = (sub & 1) << 3;

#pragma unroll 4
    for (int ks = 0; ks < 8; ++ks) {
        int kc = ks >> 2;
        int ka = ks * 16 + a_kof;
        int kb = ks * 16 + b_kof;
        uint32_t aoff = (kc << 14) + SWZ(a_row * 128 + (ka & 63) * 2);
        uint32_t baddr = bB + (kc << 14) + SWZ(b_n * 128 + (kb & 63) * 2);
        uint32_t ah0[4], ah1[4], al0[4], al1[4];
        ldsm4(ah0, aHi + aoff);
        ldsm4(ah1, aHi + aoff + 2048);
        ldsm4(al0, aLo + aoff);
        ldsm4(al1, aLo + aoff + 2048);
        uint32_t bf[4][4];
#pragma unroll
        for (int p = 0; p < 4; ++p) ldsm4(bf[p], baddr + p * 2048);
#pragma unroll
        for (int p = 0; p < 4; ++p) {
#pragma unroll
            for (int h = 0; h < 2; ++h) {
                int nt = p * 2 + h;
                mma16816(acc[0][nt], ah0, &bf[p][h * 2]);
                mma16816(acc[1][nt], ah1, &bf[p][h * 2]);
                mma16816(acc[0][nt], al0, &bf[p][h * 2]);
                mma16816(acc[1][nt], al1, &bf[p][h * 2]);
            }
        }
    }
}

__global__ void __launch_bounds__(256, 1)
mlp_kernel(const int* __restrict__ src,
           const float* __restrict__ b1, const float* __restrict__ b2, int ntiles) {
    extern __shared__ char smem[];
    uint32_t smem_base = smem_u32(smem);
    int tid = threadIdx.x;
    int wid = tid >> 5;
    int lane = tid & 31;

    float* b1s = (float*)(smem + SM_B1);
    float* b2s = (float*)(smem + SM_B2);
    if (tid < 128) { b1s[tid] = b1[tid]; b2s[tid] = b2[tid]; }

    // async copy of weight images (65536 bytes), overlapped with first H build
    {
        const char* ws = (const char*)g_Wimg;
        for (int i = tid; i < 4096; i += 256) {
            uint32_t d = smem_base + SM_W + i * 16;
            asm volatile("cp.async.cg.shared.global [%0], [%1], 16;"
                         :: "r"(d), "l"(ws + (size_t)i * 16) : "memory");
        }
        asm volatile("cp.async.commit_group;" ::: "memory");
    }

    int m_warp = (wid >> 1) * 32;
    int n_warp = (wid & 1) * 64;
    int ql = lane & 3, qr = lane >> 2;

    for (int tile = blockIdx.x; tile < ntiles; tile += gridDim.x) {
        int base = tile * 128;

        // build H tile (hi/lo fp16, SW128-swizzled, 2 K-chunks)
#pragma unroll 1
        for (int j = 0; j < 8; ++j) {
            int g = j * 256 + tid;           // 0..2047 groups of 8 cols
            int m = g >> 4;
            int k0 = (g & 15) * 8;
            int row = base + m;
            int s = __ldg(&src[row]);
            const float4* l4 = (const float4*)(g_lgX + (size_t)row * DD + k0);
            const float4* a4 = (const float4*)(g_A + (size_t)s * DD + k0);
            float4 p = l4[0], q = l4[1], pa = a4[0], qa = a4[1];
            float v[8] = {p.x + pa.x, p.y + pa.y, p.z + pa.z, p.w + pa.w,
                          q.x + qa.x, q.y + qa.y, q.z + qa.z, q.w + qa.w};
            uint32_t hw[4], lw[4];
#pragma unroll
            for (int t = 0; t < 4; ++t) {
                __half2 h2 = __float22half2_rn(make_float2(v[2 * t], v[2 * t + 1]));
                float rx = v[2 * t]     - __half2float(h2.x);
                float ry = v[2 * t + 1] - __half2float(h2.y);
                __half2 l2 = __float22half2_rn(make_float2(rx, ry));
                hw[t] = *reinterpret_cast<uint32_t*>(&h2);
                lw[t] = *reinterpret_cast<uint32_t*>(&l2);
            }
            int ch = k0 >> 6;
            int boff = m * 128 + (k0 & 63) * 2;
            int sw = SWZ(boff);
            *(uint4*)(smem + SM_H + ch * 16384 + sw)   = make_uint4(hw[0], hw[1], hw[2], hw[3]);
            *(uint4*)(smem + SM_HLO + ch * 16384 + sw) = make_uint4(lw[0], lw[1], lw[2], lw[3]);
        }
        asm volatile("cp.async.wait_group 0;" ::: "memory");
        __syncthreads();

        float acc[2][8][4];
#pragma unroll
        for (int mt = 0; mt < 2; ++mt)
#pragma unroll
            for (int nt = 0; nt < 8; ++nt)
#pragma unroll
                for (int c = 0; c < 4; ++c) acc[mt][nt][c] = 0.f;

        // GEMM1: T = H @ W1
        gemm128(smem_base + SM_H, smem_base + SM_HLO, smem_base + SM_W,
                lane, m_warp, n_warp, acc);
        __syncthreads();

        // epilogue 1: T = relu(acc + b1) -> fp16 hi/lo back into H images
#pragma unroll
        for (int mt = 0; mt < 2; ++mt) {
#pragma unroll
            for (int nt = 0; nt < 8; ++nt) {
                int col = n_warp + nt * 8 + ql * 2;
                float2 bb = *(const float2*)(b1s + col);
                int ch = col >> 6;
                int cbyte = (col & 63) * 2;
#pragma unroll
                for (int h = 0; h < 2; ++h) {
                    int row = m_warp + mt * 16 + qr + h * 8;
                    float vx = fmaxf(acc[mt][nt][h * 2]     + bb.x, 0.f);
                    float vy = fmaxf(acc[mt][nt][h * 2 + 1] + bb.y, 0.f);
                    __half2 h2 = __float22half2_rn(make_float2(vx, vy));
                    float rx = vx - __half2float(h2.x);
                    float ry = vy - __half2float(h2.y);
                    __half2 l2 = __float22half2_rn(make_float2(rx, ry));
                    int sw = SWZ(row * 128 + cbyte);
                    *(uint32_t*)(smem + SM_H + ch * 16384 + sw)   = *reinterpret_cast<uint32_t*>(&h2);
                    *(uint32_t*)(smem + SM_HLO + ch * 16384 + sw) = *reinterpret_cast<uint32_t*>(&l2);
                    acc[mt][nt][h * 2] = 0.f;
                    acc[mt][nt][h * 2 + 1] = 0.f;
                }
            }
        }
        __syncthreads();

        // GEMM2: out = T @ W2
        gemm128(smem_base + SM_H, smem_base + SM_HLO, smem_base + SM_W + 32768,
                lane, m_warp, n_warp, acc);

        // epilogue 2: lgX = acc + b2 (direct global store)
#pragma unroll
        for (int mt = 0; mt < 2; ++mt) {
#pragma unroll
            for (int nt = 0; nt < 8; ++nt) {
                int col = n_warp + nt * 8 + ql * 2;
                float2 bb = *(const float2*)(b2s + col);
#pragma unroll
                for (int h = 0; h < 2; ++h) {
                    int row = base + m_warp + mt * 16 + qr + h * 8;
                    float2 o;
                    o.x = acc[mt][nt][h * 2]     + bb.x;
                    o.y = acc[mt][nt][h * 2 + 1] + bb.y;
                    *(float2*)(g_lgX + (size_t)row * DD + col) = o;
                }
            }
        }
        __syncthreads();   // GEMM2 smem reads done before next tile's H build
    }
}

// ---------------- output: relu(scatter_mean over dst) ----------------
__global__ void __launch_bounds__(256) out_kernel(float* __restrict__ out, int Nn) {
    int w = (blockIdx.x * blockDim.x + threadIdx.x) >> 5;
    int lane = threadIdx.x & 31;
    if (w >= Nn) return;
    float4 acc = make_float4(0.f, 0.f, 0.f, 0.f);
    int n = min(g_cnt[w], CAP);
    int nb = min(n, 32);
    int myid = (lane < nb) ? g_buckets[w * CAP + lane] : 0;
    int e = 0;
    for (; e + 2 <= nb; e += 2) {
        int i0 = __shfl_sync(0xffffffffu, myid, e);
        int i1 = __shfl_sync(0xffffffffu, myid, e + 1);
        float4 l0 = *(const float4*)(g_lgX + (size_t)i0 * DD + lane * 4);
        float4 l1 = *(const float4*)(g_lgX + (size_t)i1 * DD + lane * 4);
        acc.x += l0.x + l1.x; acc.y += l0.y + l1.y;
        acc.z += l0.z + l1.z; acc.w += l0.w + l1.w;
    }
    for (; e < n; e++) {
        int i0 = (e < 32) ? __shfl_sync(0xffffffffu, myid, e) : g_buckets[w * CAP + e];
        float4 l0 = *(const float4*)(g_lgX + (size_t)i0 * DD + lane * 4);
        acc.x += l0.x; acc.y += l0.y; acc.z += l0.z; acc.w += l0.w;
    }
    float inv = 1.0f / fmaxf((float)g_cnt[w], 1.0f);
    float4 o;
    o.x = fmaxf(acc.x * inv, 0.f);
    o.y = fmaxf(acc.y * inv, 0.f);
    o.z = fmaxf(acc.z * inv, 0.f);
    o.w = fmaxf(acc.w * inv, 0.f);
    *(float4*)(out + w * DD + lane * 4) = o;
}

// ---------------- launcher ----------------
extern "C" void kernel_launch(void* const* d_in, const int* in_sizes, int n_in,
                              void* d_out, int out_size) {
    const float* x  = (const float*)d_in[0];
    const int*   ei = (const int*)d_in[1];
    const float* W1 = (const float*)d_in[4];
    const float* b1 = (const float*)d_in[5];
    const float* W2 = (const float*)d_in[6];
    const float* b2 = (const float*)d_in[7];
    float* out = (float*)d_out;

    int E  = in_sizes[1] / 2;
    int Nn = in_sizes[0] / DD;
    const int* src = ei;
    const int* dst = ei + E;
    int ntiles = E / 128;

    cudaFuncSetAttribute(mlp_kernel,
                         cudaFuncAttributeMaxDynamicSharedMemorySize, SM_TOTAL);

    prep_w_kernel<<<64, 256>>>(W1, W2);
    zero_cnt_kernel<<<(Nn + 255) / 256, 256>>>(Nn);
    fill_kernel<<<(E + 255) / 256, 256>>>(dst, E);

    // iteration 0: fused init + aggregation
    agg0_kernel<<<(Nn * 32 + 255) / 256, 256>>>(x, src, Nn);
    mlp_kernel<<<152, 256, SM_TOTAL>>>(src, b1, b2, ntiles);

    for (int it = 1; it < 3; ++it) {
        agg_kernel<<<(Nn * 32 + 255) / 256, 256>>>(x, Nn);
        mlp_kernel<<<152, 256, SM_TOTAL>>>(src, b1, b2, ntiles);
    }

    out_kernel<<<(Nn * 32 + 255) / 256, 256>>>(out, Nn);
}

// round 6
// speedup vs baseline: 5.0712x; 1.2875x over previous
#include <cuda_runtime.h>
#include <cuda_fp16.h>
#include <cstdint>

// Problem shape (fixed by the dataset)
#define DD 128
#define MAXN 10000
#define MAXE 80000
#define CAP 128           // in-degree bucket capacity (indeg ~ Poisson(8))

// ---------------- device scratch ----------------
__device__ float g_lgX[MAXE * DD];            // line-graph node features [E,128]
__device__ float g_A[MAXN * DD];              // per-node aggregate       [N,128]
__device__ int   g_cnt[MAXN];                 // in-degree
__device__ int   g_buckets[MAXN * CAP];       // in-edge ids per node
// W images: [W1 | W2]; each 128x128 fp16 stored transposed (BT[n][k] = W[k][n])
// in two 64-col K-chunks of 16KB, SW128-swizzled rows.
__device__ __half g_Wimg[2 * 16384];

#define SWZ(x) ((x) ^ (((x) >> 3) & 0x70))

__device__ __forceinline__ uint32_t smem_u32(const void* p) {
    uint32_t a;
    asm("{ .reg .u64 t; cvta.to.shared.u64 t, %1; cvt.u32.u64 %0, t; }" : "=r"(a) : "l"(p));
    return a;
}
__device__ __forceinline__ void ldsm4(uint32_t* r, uint32_t addr) {
    asm volatile("ldmatrix.sync.aligned.m8n8.x4.shared.b16 {%0,%1,%2,%3}, [%4];"
        : "=r"(r[0]), "=r"(r[1]), "=r"(r[2]), "=r"(r[3]) : "r"(addr));
}
__device__ __forceinline__ void mma16816(float* c, const uint32_t* a, const uint32_t* b) {
    asm volatile("mma.sync.aligned.m16n8k16.row.col.f32.f16.f16.f32 "
        "{%0,%1,%2,%3}, {%4,%5,%6,%7}, {%8,%9}, {%0,%1,%2,%3};"
        : "+f"(c[0]), "+f"(c[1]), "+f"(c[2]), "+f"(c[3])
        : "r"(a[0]), "r"(a[1]), "r"(a[2]), "r"(a[3]), "r"(b[0]), "r"(b[1]));
}

// ---------------- bucket CSR build ----------------
__global__ void zero_cnt_kernel(int n) {
    int i = blockIdx.x * blockDim.x + threadIdx.x;
    if (i < n) g_cnt[i] = 0;
}
__global__ void fill_kernel(const int* __restrict__ dst, int E) {
    int i = blockIdx.x * blockDim.x + threadIdx.x;
    if (i < E) {
        int v = dst[i];
        int p = atomicAdd(&g_cnt[v], 1);
        if (p < CAP) g_buckets[v * CAP + p] = i;
    }
}

// ---------------- W image precompute (fp16, transposed, swizzled) ----------------
__global__ void prep_w_kernel(const float* __restrict__ W1, const float* __restrict__ W2) {
    int idx = blockIdx.x * blockDim.x + threadIdx.x;   // 0..16383
    if (idx >= 16384) return;
    int n = idx >> 7, k = idx & 127;
    int chunk = k >> 6, kk = k & 63;
    int boff = n * 128 + kk * 2;
    int pos = chunk * 8192 + (SWZ(boff) >> 1);
    g_Wimg[pos]         = __float2half(W1[k * 128 + n]);
    g_Wimg[16384 + pos] = __float2half(W2[k * 128 + n]);
}

// ---------------- fused init + aggregation (iteration 0) ----------------
__global__ void __launch_bounds__(256) agg0_kernel(const float* __restrict__ x,
                                                   const int* __restrict__ src, int Nn) {
    int w = (blockIdx.x * blockDim.x + threadIdx.x) >> 5;
    int lane = threadIdx.x & 31;
    if (w >= Nn) return;
    const float4* x4 = (const float4*)x;
    float4 xv = x4[w * 32 + lane];
    float4 acc = make_float4(0.f, 0.f, 0.f, 0.f);
    int n = min(g_cnt[w], CAP);
    int nb = min(n, 32);
    int myid = (lane < nb) ? g_buckets[w * CAP + lane] : 0;
    int mysrc = (lane < nb) ? __ldg(&src[myid]) : 0;
    int e = 0;
    for (; e + 2 <= nb; e += 2) {
        int i0 = __shfl_sync(0xffffffffu, myid, e);
        int i1 = __shfl_sync(0xffffffffu, myid, e + 1);
        int s0 = __shfl_sync(0xffffffffu, mysrc, e);
        int s1 = __shfl_sync(0xffffffffu, mysrc, e + 1);
        float4 a0 = x4[s0 * 32 + lane];
        float4 a1 = x4[s1 * 32 + lane];
        float4 l0, l1;
        l0.x = 0.5f * (a0.x + xv.x); l0.y = 0.5f * (a0.y + xv.y);
        l0.z = 0.5f * (a0.z + xv.z); l0.w = 0.5f * (a0.w + xv.w);
        l1.x = 0.5f * (a1.x + xv.x); l1.y = 0.5f * (a1.y + xv.y);
        l1.z = 0.5f * (a1.z + xv.z); l1.w = 0.5f * (a1.w + xv.w);
        *(float4*)(g_lgX + (size_t)i0 * DD + lane * 4) = l0;
        *(float4*)(g_lgX + (size_t)i1 * DD + lane * 4) = l1;
        acc.x += fmaxf(l0.x + xv.x, 0.f) + fmaxf(l1.x + xv.x, 0.f);
        acc.y += fmaxf(l0.y + xv.y, 0.f) + fmaxf(l1.y + xv.y, 0.f);
        acc.z += fmaxf(l0.z + xv.z, 0.f) + fmaxf(l1.z + xv.z, 0.f);
        acc.w += fmaxf(l0.w + xv.w, 0.f) + fmaxf(l1.w + xv.w, 0.f);
    }
    for (; e < n; e++) {
        int i0 = (e < 32) ? __shfl_sync(0xffffffffu, myid, e) : g_buckets[w * CAP + e];
        int s0 = __ldg(&src[i0]);
        float4 a0 = x4[s0 * 32 + lane];
        float4 l0;
        l0.x = 0.5f * (a0.x + xv.x); l0.y = 0.5f * (a0.y + xv.y);
        l0.z = 0.5f * (a0.z + xv.z); l0.w = 0.5f * (a0.w + xv.w);
        *(float4*)(g_lgX + (size_t)i0 * DD + lane * 4) = l0;
        acc.x += fmaxf(l0.x + xv.x, 0.f);
        acc.y += fmaxf(l0.y + xv.y, 0.f);
        acc.z += fmaxf(l0.z + xv.z, 0.f);
        acc.w += fmaxf(l0.w + xv.w, 0.f);
    }
    *(float4*)(g_A + w * DD + lane * 4) = acc;
}

// ---------------- aggregation (iterations 1,2) ----------------
__global__ void __launch_bounds__(256) agg_kernel(const float* __restrict__ x, int Nn) {
    int w = (blockIdx.x * blockDim.x + threadIdx.x) >> 5;
    int lane = threadIdx.x & 31;
    if (w >= Nn) return;
    const float4* x4 = (const float4*)x;
    float4 xv = x4[w * 32 + lane];
    float4 acc = make_float4(0.f, 0.f, 0.f, 0.f);
    int n = min(g_cnt[w], CAP);
    int nb = min(n, 32);
    int myid = (lane < nb) ? g_buckets[w * CAP + lane] : 0;
    int e = 0;
    for (; e + 2 <= nb; e += 2) {
        int i0 = __shfl_sync(0xffffffffu, myid, e);
        int i1 = __shfl_sync(0xffffffffu, myid, e + 1);
        float4 l0 = *(const float4*)(g_lgX + (size_t)i0 * DD + lane * 4);
        float4 l1 = *(const float4*)(g_lgX + (size_t)i1 * DD + lane * 4);
        acc.x += fmaxf(l0.x + xv.x, 0.f) + fmaxf(l1.x + xv.x, 0.f);
        acc.y += fmaxf(l0.y + xv.y, 0.f) + fmaxf(l1.y + xv.y, 0.f);
        acc.z += fmaxf(l0.z + xv.z, 0.f) + fmaxf(l1.z + xv.z, 0.f);
        acc.w += fmaxf(l0.w + xv.w, 0.f) + fmaxf(l1.w + xv.w, 0.f);
    }
    for (; e < n; e++) {
        int i0 = (e < 32) ? __shfl_sync(0xffffffffu, myid, e) : g_buckets[w * CAP + e];
        float4 l0 = *(const float4*)(g_lgX + (size_t)i0 * DD + lane * 4);
        acc.x += fmaxf(l0.x + xv.x, 0.f);
        acc.y += fmaxf(l0.y + xv.y, 0.f);
        acc.z += fmaxf(l0.z + xv.z, 0.f);
        acc.w += fmaxf(l0.w + xv.w, 0.f);
    }
    *(float4*)(g_A + w * DD + lane * 4) = acc;
}

// ---------------- fused MLP via fp16 HMMA (persistent, occ-2, 64-row tiles) ----------------
// SMEM (bytes): W1 32K | W2 32K | Hhi 16K (2 chunks x 8K) | Hlo 16K | b1 | b2
#define SM_W    0
#define SM_H    65536
#define SM_HLO  81920
#define SM_B1   98304
#define SM_B2   98816
#define SM_TOTAL 99328
#define TILE_M  64

// D(64x128) = (Ahi + Alo) @ B;  A chunks 8KB, B chunks 16KB
__device__ __forceinline__ void gemm64(
    uint32_t aHi, uint32_t aLo, uint32_t bB,
    int lane, int m_warp, int n_warp, float acc[2][4][4])
{
    int sub = lane >> 3, rr = lane & 7;
    int a_row = m_warp + ((sub & 1) << 3) + rr;
    int a_kof = (sub >> 1) << 3;
    int b_n   = n_warp + ((sub >> 1) << 3) + rr;
    int b_kof = (sub & 1) << 3;

#pragma unroll 4
    for (int ks = 0; ks < 8; ++ks) {
        int kc = ks >> 2;
        int ka = ks * 16 + a_kof;
        int kb = ks * 16 + b_kof;
        uint32_t aoff = (kc << 13) + SWZ(a_row * 128 + (ka & 63) * 2);
        uint32_t baddr = bB + (kc << 14) + SWZ(b_n * 128 + (kb & 63) * 2);
        uint32_t ah0[4], ah1[4], al0[4], al1[4];
        ldsm4(ah0, aHi + aoff);
        ldsm4(ah1, aHi + aoff + 2048);       // +16 rows
        ldsm4(al0, aLo + aoff);
        ldsm4(al1, aLo + aoff + 2048);
        uint32_t bf[2][4];
        ldsm4(bf[0], baddr);
        ldsm4(bf[1], baddr + 2048);          // +16 n
#pragma unroll
        for (int p = 0; p < 2; ++p) {
#pragma unroll
            for (int h = 0; h < 2; ++h) {
                int nt = p * 2 + h;
                mma16816(acc[0][nt], ah0, &bf[p][h * 2]);
                mma16816(acc[1][nt], ah1, &bf[p][h * 2]);
                mma16816(acc[0][nt], al0, &bf[p][h * 2]);
                mma16816(acc[1][nt], al1, &bf[p][h * 2]);
            }
        }
    }
}

__global__ void __launch_bounds__(256, 2)
mlp_kernel(const int* __restrict__ src,
           const float* __restrict__ b1, const float* __restrict__ b2, int ntiles) {
    extern __shared__ char smem[];
    uint32_t smem_base = smem_u32(smem);
    int tid = threadIdx.x;
    int wid = tid >> 5;
    int lane = tid & 31;

    float* b1s = (float*)(smem + SM_B1);
    float* b2s = (float*)(smem + SM_B2);
    if (tid < 128) { b1s[tid] = b1[tid]; b2s[tid] = b2[tid]; }

    // async copy of weight images (65536 bytes), overlapped with first H build
    {
        const char* ws = (const char*)g_Wimg;
        for (int i = tid; i < 4096; i += 256) {
            uint32_t d = smem_base + SM_W + i * 16;
            asm volatile("cp.async.cg.shared.global [%0], [%1], 16;"
                         :: "r"(d), "l"(ws + (size_t)i * 16) : "memory");
        }
        asm volatile("cp.async.commit_group;" ::: "memory");
    }

    int m_warp = (wid >> 2) * 32;        // {0,32}
    int n_warp = (wid & 3) * 32;         // {0,32,64,96}
    int ql = lane & 3, qr = lane >> 2;

    for (int tile = blockIdx.x; tile < ntiles; tile += gridDim.x) {
        int base = tile * TILE_M;

        // build H tile (hi/lo fp16, SW128-swizzled, 2 K-chunks of 8KB)
#pragma unroll
        for (int j = 0; j < 4; ++j) {
            int g = j * 256 + tid;           // 0..1023 groups of 8 cols
            int m = g >> 4;
            int k0 = (g & 15) * 8;
            int row = base + m;
            int s = __ldg(&src[row]);
            const float4* l4 = (const float4*)(g_lgX + (size_t)row * DD + k0);
            const float4* a4 = (const float4*)(g_A + (size_t)s * DD + k0);
            float4 p = l4[0], q = l4[1], pa = a4[0], qa = a4[1];
            float v[8] = {p.x + pa.x, p.y + pa.y, p.z + pa.z, p.w + pa.w,
                          q.x + qa.x, q.y + qa.y, q.z + qa.z, q.w + qa.w};
            uint32_t hw[4], lw[4];
#pragma unroll
            for (int t = 0; t < 4; ++t) {
                __half2 h2 = __float22half2_rn(make_float2(v[2 * t], v[2 * t + 1]));
                float rx = v[2 * t]     - __half2float(h2.x);
                float ry = v[2 * t + 1] - __half2float(h2.y);
                __half2 l2 = __float22half2_rn(make_float2(rx, ry));
                hw[t] = *reinterpret_cast<uint32_t*>(&h2);
                lw[t] = *reinterpret_cast<uint32_t*>(&l2);
            }
            int ch = k0 >> 6;
            int sw = SWZ(m * 128 + (k0 & 63) * 2);
            *(uint4*)(smem + SM_H + ch * 8192 + sw)   = make_uint4(hw[0], hw[1], hw[2], hw[3]);
            *(uint4*)(smem + SM_HLO + ch * 8192 + sw) = make_uint4(lw[0], lw[1], lw[2], lw[3]);
        }
        asm volatile("cp.async.wait_group 0;" ::: "memory");
        __syncthreads();

        float acc[2][4][4];
#pragma unroll
        for (int mt = 0; mt < 2; ++mt)
#pragma unroll
            for (int nt = 0; nt < 4; ++nt)
#pragma unroll
                for (int c = 0; c < 4; ++c) acc[mt][nt][c] = 0.f;

        // GEMM1: T = H @ W1
        gemm64(smem_base + SM_H, smem_base + SM_HLO, smem_base + SM_W,
               lane, m_warp, n_warp, acc);
        __syncthreads();

        // epilogue 1: T = relu(acc + b1) -> fp16 hi/lo back into H images
#pragma unroll
        for (int mt = 0; mt < 2; ++mt) {
#pragma unroll
            for (int nt = 0; nt < 4; ++nt) {
                int col = n_warp + nt * 8 + ql * 2;
                float2 bb = *(const float2*)(b1s + col);
                int ch = col >> 6;
                int cbyte = (col & 63) * 2;
#pragma unroll
                for (int h = 0; h < 2; ++h) {
                    int row = m_warp + mt * 16 + qr + h * 8;
                    float vx = fmaxf(acc[mt][nt][h * 2]     + bb.x, 0.f);
                    float vy = fmaxf(acc[mt][nt][h * 2 + 1] + bb.y, 0.f);
                    __half2 h2 = __float22half2_rn(make_float2(vx, vy));
                    float rx = vx - __half2float(h2.x);
                    float ry = vy - __half2float(h2.y);
                    __half2 l2 = __float22half2_rn(make_float2(rx, ry));
                    int sw = SWZ(row * 128 + cbyte);
                    *(uint32_t*)(smem + SM_H + ch * 8192 + sw)   = *reinterpret_cast<uint32_t*>(&h2);
                    *(uint32_t*)(smem + SM_HLO + ch * 8192 + sw) = *reinterpret_cast<uint32_t*>(&l2);
                    acc[mt][nt][h * 2] = 0.f;
                    acc[mt][nt][h * 2 + 1] = 0.f;
                }
            }
        }
        __syncthreads();

        // GEMM2: out = T @ W2
        gemm64(smem_base + SM_H, smem_base + SM_HLO, smem_base + SM_W + 32768,
               lane, m_warp, n_warp, acc);

        // epilogue 2: lgX = acc + b2 (direct global store)
#pragma unroll
        for (int mt = 0; mt < 2; ++mt) {
#pragma unroll
            for (int nt = 0; nt < 4; ++nt) {
                int col = n_warp + nt * 8 + ql * 2;
                float2 bb = *(const float2*)(b2s + col);
#pragma unroll
                for (int h = 0; h < 2; ++h) {
                    int row = base + m_warp + mt * 16 + qr + h * 8;
                    float2 o;
                    o.x = acc[mt][nt][h * 2]     + bb.x;
                    o.y = acc[mt][nt][h * 2 + 1] + bb.y;
                    *(float2*)(g_lgX + (size_t)row * DD + col) = o;
                }
            }
        }
        __syncthreads();   // GEMM2 smem reads done before next tile's H build
    }
}

// ---------------- output: relu(scatter_mean over dst) ----------------
__global__ void __launch_bounds__(256) out_kernel(float* __restrict__ out, int Nn) {
    int w = (blockIdx.x * blockDim.x + threadIdx.x) >> 5;
    int lane = threadIdx.x & 31;
    if (w >= Nn) return;
    float4 acc = make_float4(0.f, 0.f, 0.f, 0.f);
    int n = min(g_cnt[w], CAP);
    int nb = min(n, 32);
    int myid = (lane < nb) ? g_buckets[w * CAP + lane] : 0;
    int e = 0;
    for (; e + 2 <= nb; e += 2) {
        int i0 = __shfl_sync(0xffffffffu, myid, e);
        int i1 = __shfl_sync(0xffffffffu, myid, e + 1);
        float4 l0 = *(const float4*)(g_lgX + (size_t)i0 * DD + lane * 4);
        float4 l1 = *(const float4*)(g_lgX + (size_t)i1 * DD + lane * 4);
        acc.x += l0.x + l1.x; acc.y += l0.y + l1.y;
        acc.z += l0.z + l1.z; acc.w += l0.w + l1.w;
    }
    for (; e < n; e++) {
        int i0 = (e < 32) ? __shfl_sync(0xffffffffu, myid, e) : g_buckets[w * CAP + e];
        float4 l0 = *(const float4*)(g_lgX + (size_t)i0 * DD + lane * 4);
        acc.x += l0.x; acc.y += l0.y; acc.z += l0.z; acc.w += l0.w;
    }
    float inv = 1.0f / fmaxf((float)g_cnt[w], 1.0f);
    float4 o;
    o.x = fmaxf(acc.x * inv, 0.f);
    o.y = fmaxf(acc.y * inv, 0.f);
    o.z = fmaxf(acc.z * inv, 0.f);
    o.w = fmaxf(acc.w * inv, 0.f);
    *(float4*)(out + w * DD + lane * 4) = o;
}

// ---------------- launcher ----------------
extern "C" void kernel_launch(void* const* d_in, const int* in_sizes, int n_in,
                              void* d_out, int out_size) {
    const float* x  = (const float*)d_in[0];
    const int*   ei = (const int*)d_in[1];
    const float* W1 = (const float*)d_in[4];
    const float* b1 = (const float*)d_in[5];
    const float* W2 = (const float*)d_in[6];
    const float* b2 = (const float*)d_in[7];
    float* out = (float*)d_out;

    int E  = in_sizes[1] / 2;
    int Nn = in_sizes[0] / DD;
    const int* src = ei;
    const int* dst = ei + E;
    int ntiles = E / TILE_M;

    cudaFuncSetAttribute(mlp_kernel,
                         cudaFuncAttributeMaxDynamicSharedMemorySize, SM_TOTAL);

    prep_w_kernel<<<64, 256>>>(W1, W2);
    zero_cnt_kernel<<<(Nn + 255) / 256, 256>>>(Nn);
    fill_kernel<<<(E + 255) / 256, 256>>>(dst, E);

    // iteration 0: fused init + aggregation
    agg0_kernel<<<(Nn * 32 + 255) / 256, 256>>>(x, src, Nn);
    mlp_kernel<<<304, 256, SM_TOTAL>>>(src, b1, b2, ntiles);

    for (int it = 1; it < 3; ++it) {
        agg_kernel<<<(Nn * 32 + 255) / 256, 256>>>(x, Nn);
        mlp_kernel<<<304, 256, SM_TOTAL>>>(src, b1, b2, ntiles);
    }

    out_kernel<<<(Nn * 32 + 255) / 256, 256>>>(out, Nn);
}